// round 1
// baseline (speedup 1.0000x reference)
#include <cuda_runtime.h>
#include <math.h>
#include <stdint.h>

#define BB 64
#define TT_ 1024
#define FF 512
#define II 256
#define SS 128
#define MM 64
#define NPROJ 384
#define L2E 1.4426950408889634f
#define STT 16

// ---------------- scratch (static device globals; no allocation) ----------------
__device__ float g_proj[(size_t)BB * TT_ * NPROJ];   // tanh(inputs@W_in+b)  (B*T, 384)
__device__ float g_CG [(size_t)BB * TT_ * SS];       // C * sigmoid(softmax(gate))
__device__ float g_wns[(size_t)BB * TT_ * SS];       // sensory num + gleak*vleak
__device__ float g_wds[(size_t)BB * TT_ * SS];       // sensory den + cm_t + gleak + eps
__device__ float g_RA1[SS * SS], g_RA2[SS * SS], g_RWN[SS * SS];   // recurrent, [k][j]
__device__ float g_SA1[II * SS], g_SA2[II * SS], g_SWN[II * SS];   // sensory,  [i][k]
__device__ float g_cmt[SS], g_nadd[SS], g_dadd[SS];

// ---------------- param preprocessing ----------------
__global__ void prep_kernel(const float* __restrict__ w, const float* __restrict__ sigma,
                            const float* __restrict__ mu, const float* __restrict__ erev,
                            const float* __restrict__ mask,
                            const float* __restrict__ sw, const float* __restrict__ ssig,
                            const float* __restrict__ smu, const float* __restrict__ serev,
                            const float* __restrict__ smask,
                            const float* __restrict__ gleak, const float* __restrict__ vleak,
                            const float* __restrict__ cm)
{
    int idx = blockIdx.x * blockDim.x + threadIdx.x;
    if (idx < SS * SS) {
        int j = idx / SS, k = idx % SS;
        float sg = sigma[idx], m = mu[idx];
        // sigmoid((v-mu)*sigma) = 1/(1+exp2(v*(-sg*L2E) + mu*sg*L2E))
        g_RA1[k * SS + j] = -sg * L2E;
        g_RA2[k * SS + j] = m * sg * L2E;
        g_RWN[k * SS + j] = w[idx] * mask[idx] * erev[idx];   // signed; den uses fabs
    }
    int i2 = idx - SS * SS;
    if (i2 >= 0 && i2 < II * SS) {
        float sg = ssig[i2], m = smu[i2];
        g_SA1[i2] = -sg * L2E;
        g_SA2[i2] = m * sg * L2E;
        g_SWN[i2] = sw[i2] * smask[i2] * serev[i2];
    }
    int i3 = idx - SS * SS - II * SS;
    if (i3 >= 0 && i3 < SS) {
        float c = cm[i3] * 6.0f;               // cm / (ELAPSED/ODE_UNFOLDS)
        g_cmt[i3]  = c;
        g_nadd[i3] = gleak[i3] * vleak[i3];
        g_dadd[i3] = c + gleak[i3] + 1e-8f;
    }
}

// ---------------- generic tiled SIMT GEMM (BM=128, BN=64, BK=16, 256 thr) ----------------
// C[m,n] = act(sum_k A[m,k]*B[k,n] + bias[n]); A row stride lda, B row stride ldb.
template <int ACT>
__global__ void __launch_bounds__(256) gemm_kernel(const float* __restrict__ A, int lda,
                                                   const float* __restrict__ B, int ldb,
                                                   const float* __restrict__ bias,
                                                   float* __restrict__ C, int ldc, int K)
{
    __shared__ float As[16][128];
    __shared__ float Bs[16][64];
    int tid = threadIdx.x;
    int bm = blockIdx.y * 128;
    int bn = blockIdx.x * 64;
    int tx = tid & 15, ty = tid >> 4;
    int a_m = tid >> 2;            // 0..63
    int a_k = (tid & 3) * 4;       // 0,4,8,12
    int b_k = tid >> 4;            // 0..15
    int b_n = (tid & 15) * 4;

    float acc[8][4];
#pragma unroll
    for (int i = 0; i < 8; i++)
#pragma unroll
        for (int j = 0; j < 4; j++) acc[i][j] = 0.f;

    for (int k0 = 0; k0 < K; k0 += 16) {
#pragma unroll
        for (int i = 0; i < 2; i++) {
            float4 va = *(const float4*)(A + (size_t)(bm + a_m + i * 64) * lda + k0 + a_k);
            As[a_k + 0][a_m + i * 64] = va.x;
            As[a_k + 1][a_m + i * 64] = va.y;
            As[a_k + 2][a_m + i * 64] = va.z;
            As[a_k + 3][a_m + i * 64] = va.w;
        }
        *(float4*)(&Bs[b_k][b_n]) = *(const float4*)(B + (size_t)(k0 + b_k) * ldb + bn + b_n);
        __syncthreads();
#pragma unroll
        for (int kk = 0; kk < 16; kk++) {
            float a[8], bv[4];
#pragma unroll
            for (int i = 0; i < 8; i++) a[i] = As[kk][ty * 8 + i];
#pragma unroll
            for (int j = 0; j < 4; j++) bv[j] = Bs[kk][tx * 4 + j];
#pragma unroll
            for (int i = 0; i < 8; i++)
#pragma unroll
                for (int j = 0; j < 4; j++) acc[i][j] = fmaf(a[i], bv[j], acc[i][j]);
        }
        __syncthreads();
    }
    float4 bb = *(const float4*)(bias + bn + tx * 4);
    float bv4[4] = {bb.x, bb.y, bb.z, bb.w};
#pragma unroll
    for (int i = 0; i < 8; i++) {
        int m = bm + ty * 8 + i;
        float4 o;
        float v0 = acc[i][0] + bv4[0], v1 = acc[i][1] + bv4[1];
        float v2 = acc[i][2] + bv4[2], v3 = acc[i][3] + bv4[3];
        if (ACT == 1) { v0 = tanhf(v0); v1 = tanhf(v1); v2 = tanhf(v2); v3 = tanhf(v3); }
        o.x = v0; o.y = v1; o.z = v2; o.w = v3;
        *(float4*)(C + (size_t)m * ldc + bn + tx * 4) = o;
    }
}

// ---------------- softmax over T (axis=1) + fold sigmoid into CG ----------------
__global__ void __launch_bounds__(128) softmax_cg_kernel()
{
    int b = blockIdx.x;
    int s = threadIdx.x;
    const float* gp = g_proj + (size_t)b * TT_ * NPROJ + II + s;
    float m = -1e30f;
#pragma unroll 4
    for (int t = 0; t < TT_; t++) m = fmaxf(m, gp[(size_t)t * NPROJ]);
    float sum = 0.f;
#pragma unroll 4
    for (int t = 0; t < TT_; t++) sum += exp2f((gp[(size_t)t * NPROJ] - m) * L2E);
    float rs = __fdividef(1.f, sum);
    float* cg = g_CG + (size_t)b * TT_ * SS + s;
#pragma unroll 4
    for (int t = 0; t < TT_; t++) {
        float p = exp2f((gp[(size_t)t * NPROJ] - m) * L2E) * rs;
        float sg = __fdividef(1.f, 1.f + exp2f(-p * L2E));
        cg[(size_t)t * SS] *= sg;
    }
}

// ---------------- sensory precompute: per (b,t,k) w_num_s/w_den_s ----------------
__global__ void __launch_bounds__(128) sensory_kernel()
{
    int blk = blockIdx.x;
    int b = blk >> 6;                  // T/STT = 64
    int t0 = (blk & 63) * STT;
    __shared__ float sh[STT][II];
    int tid = threadIdx.x;
    size_t rowbase = (size_t)b * TT_ + t0;
    for (int idx = tid; idx < STT * II; idx += 128) {
        int tt = idx >> 8, i = idx & 255;
        sh[tt][i] = g_proj[(rowbase + tt) * NPROJ + i];
    }
    __syncthreads();
    int k = tid;
    float num[STT], den[STT];
#pragma unroll
    for (int tt = 0; tt < STT; tt++) { num[tt] = 0.f; den[tt] = 0.f; }
    for (int i = 0; i < II; i++) {
        float a1 = g_SA1[i * SS + k];
        float a2 = g_SA2[i * SS + k];
        float wv = g_SWN[i * SS + k];
        float aw = fabsf(wv);
#pragma unroll
        for (int tt = 0; tt < STT; tt++) {
            float x = fmaf(sh[tt][i], a1, a2);
            float r = __fdividef(1.f, 1.f + exp2f(x));
            num[tt] = fmaf(wv, r, num[tt]);
            den[tt] = fmaf(aw, r, den[tt]);
        }
    }
    float na = g_nadd[k], da = g_dadd[k];
#pragma unroll
    for (int tt = 0; tt < STT; tt++) {
        size_t row = rowbase + tt;
        g_wns[row * SS + k] = num[tt] + na;
        g_wds[row * SS + k] = den[tt] + da;
    }
}

// ---------------- sequential ODE scan: 1 CTA per batch ----------------
#define SCAN_SMEM ((3 * 128 * 132 + 128 + 512) * 4)

__global__ void __launch_bounds__(256, 1) scan_kernel(const float* __restrict__ v0,
                                                      float* __restrict__ fused_out,
                                                      float* __restrict__ vfinal)
{
    extern __shared__ float smem[];
    float* ra1  = smem;                    // [128][132]
    float* ra2  = ra1 + 128 * 132;
    float* wnp  = ra2 + 128 * 132;
    float* sv   = wnp + 128 * 132;         // 128
    float* snum = sv + 128;                // 256
    float* sden = snum + 256;              // 256

    int b = blockIdx.x;
    int tid = threadIdx.x;
    int k = tid & 127;
    int h = tid >> 7;

    for (int idx = tid; idx < SS * SS; idx += 256) {
        int kk = idx >> 7, j = idx & 127;
        ra1[kk * 132 + j] = g_RA1[idx];
        ra2[kk * 132 + j] = g_RA2[idx];
        wnp[kk * 132 + j] = g_RWN[idx];
    }
    if (h == 0) sv[k] = v0[b * SS + k];
    float cmt = g_cmt[k];
    __syncthreads();

    const float* base1 = ra1 + k * 132 + h * 64;
    const float* base2 = ra2 + k * 132 + h * 64;
    const float* basew = wnp + k * 132 + h * 64;
    const float* svb = sv + h * 64;

    float vk = sv[k];                       // h==0 threads keep the live copy
    size_t row = (size_t)b * TT_;

#pragma unroll 1
    for (int t = 0; t < TT_; t++, row++) {
        float wnsk = 0.f, wdsk = 0.f, cgk = 0.f;
        if (h == 0) {
            wnsk = g_wns[row * SS + k];
            wdsk = g_wds[row * SS + k];
            cgk  = g_CG [row * SS + k];
        }
#pragma unroll 1
        for (int u = 0; u < 6; u++) {
            float num = 0.f, den = 0.f;
#pragma unroll
            for (int q = 0; q < 16; q++) {
                float4 v4 = *(const float4*)(svb + q * 4);
                float4 a1 = *(const float4*)(base1 + q * 4);
                float4 a2 = *(const float4*)(base2 + q * 4);
                float4 w4 = *(const float4*)(basew + q * 4);
                float r;
                r = __fdividef(1.f, 1.f + exp2f(fmaf(v4.x, a1.x, a2.x)));
                num = fmaf(w4.x, r, num); den = fmaf(fabsf(w4.x), r, den);
                r = __fdividef(1.f, 1.f + exp2f(fmaf(v4.y, a1.y, a2.y)));
                num = fmaf(w4.y, r, num); den = fmaf(fabsf(w4.y), r, den);
                r = __fdividef(1.f, 1.f + exp2f(fmaf(v4.z, a1.z, a2.z)));
                num = fmaf(w4.z, r, num); den = fmaf(fabsf(w4.z), r, den);
                r = __fdividef(1.f, 1.f + exp2f(fmaf(v4.w, a1.w, a2.w)));
                num = fmaf(w4.w, r, num); den = fmaf(fabsf(w4.w), r, den);
            }
            snum[h * SS + k] = num;
            sden[h * SS + k] = den;
            __syncthreads();
            if (h == 0) {
                float nt = snum[k] + snum[SS + k];
                float dt = sden[k] + sden[SS + k];
                float nn = fmaf(cmt, vk, wnsk + nt);
                float dd = wdsk + dt;            // already includes cm_t+gleak+eps
                vk = nn * __fdividef(1.f, dd);
                sv[k] = vk;
            }
            __syncthreads();
        }
        if (h == 0) fused_out[row * SS + k] = vk * cgk;
    }
    if (h == 0) vfinal[b * SS + k] = vk;
}

// ---------------- launch ----------------
extern "C" void kernel_launch(void* const* d_in, const int* in_sizes, int n_in,
                              void* d_out, int out_size)
{
    const float* inputs    = (const float*)d_in[0];
    const float* ode_state = (const float*)d_in[1];
    const float* W_in      = (const float*)d_in[2];
    const float* b_in      = (const float*)d_in[3];
    const float* W_c       = (const float*)d_in[4];
    const float* b_c       = (const float*)d_in[5];
    const float* W_out     = (const float*)d_in[6];
    const float* b_out     = (const float*)d_in[7];
    const float* gleak     = (const float*)d_in[8];
    const float* vleak     = (const float*)d_in[9];
    const float* cm        = (const float*)d_in[10];
    const float* w         = (const float*)d_in[11];
    const float* sigma     = (const float*)d_in[12];
    const float* mu        = (const float*)d_in[13];
    const float* sw        = (const float*)d_in[14];
    const float* ssig      = (const float*)d_in[15];
    const float* smu       = (const float*)d_in[16];
    const float* erev      = (const float*)d_in[17];
    const float* serev     = (const float*)d_in[18];
    const float* mask      = (const float*)d_in[19];
    const float* smask     = (const float*)d_in[20];

    float* out      = (float*)d_out;                          // (B,T,M)
    float* vfinal   = out + (size_t)BB * TT_ * MM;            // (B,S)
    float* fusedout = vfinal + (size_t)BB * SS;               // (B,T,S)

    float *p_proj, *p_cg;
    cudaGetSymbolAddress((void**)&p_proj, g_proj);
    cudaGetSymbolAddress((void**)&p_cg, g_CG);

    cudaFuncSetAttribute(scan_kernel, cudaFuncAttributeMaxDynamicSharedMemorySize, SCAN_SMEM);

    int prep_n = SS * SS + II * SS + SS;
    prep_kernel<<<(prep_n + 255) / 256, 256>>>(w, sigma, mu, erev, mask,
                                               sw, ssig, smu, serev, smask,
                                               gleak, vleak, cm);

    // proj = tanh(inputs @ W_in + b_in)
    gemm_kernel<1><<<dim3(NPROJ / 64, (BB * TT_) / 128), 256>>>(
        inputs, FF, W_in, NPROJ, b_in, p_proj, NPROJ, FF);

    // CG = hidden @ W_c + b_c   (hidden = proj[:, :256], lda=384)
    gemm_kernel<0><<<dim3(SS / 64, (BB * TT_) / 128), 256>>>(
        p_proj, NPROJ, W_c, SS, b_c, p_cg, SS, II);

    // CG *= sigmoid(softmax_T(gate))
    softmax_cg_kernel<<<BB, 128>>>();

    // sensory num/den precompute
    sensory_kernel<<<BB * (TT_ / STT), 128>>>();

    // sequential scan: writes fused (B,T,S) and final state directly into d_out
    scan_kernel<<<BB, 256, SCAN_SMEM>>>(ode_state, fusedout, vfinal);

    // outputs = fused @ W_out + b_out
    gemm_kernel<0><<<dim3(MM / 64, (BB * TT_) / 128), 256>>>(
        fusedout, SS, W_out, MM, b_out, out, MM, SS);
}

// round 2
// speedup vs baseline: 1.7851x; 1.7851x over previous
#include <cuda_runtime.h>
#include <math.h>
#include <stdint.h>

#define BB 64
#define TT_ 1024
#define FF 512
#define II 256
#define SS 128
#define MM 64
#define NPROJ 384
#define STT 16

// ---------------- scratch (static device globals; no allocation) ----------------
__device__ float g_proj[(size_t)BB * TT_ * NPROJ];   // tanh(inputs@W_in+b)  (B*T, 384)
__device__ float g_CG [(size_t)BB * TT_ * SS];       // C * sigmoid(softmax(gate))
__device__ float g_wns[(size_t)BB * TT_ * SS];       // sensory num + all per-k num consts
__device__ float g_wds[(size_t)BB * TT_ * SS];       // sensory den + all per-k den consts
__device__ float g_RA1[SS * SS], g_RA2[SS * SS];     // recurrent 0.5*sigma / -0.5*sigma*mu, [k][j]
__device__ float g_RWN[SS * SS];                     // 0.5*w*mask*erev, [j][k]
__device__ float g_SA1[II * SS], g_SA2[II * SS], g_SWN[II * SS];   // sensory, [i][k]
__device__ float g_cmt[SS], g_nadd[SS], g_dadd[SS];

__device__ __forceinline__ float tanh_fast(float x) {
    float r;
    asm("tanh.approx.f32 %0, %1;" : "=f"(r) : "f"(x));
    return r;
}

// ---------------- param preprocessing ----------------
// sigmoid((v-mu)*sigma) = 0.5 + 0.5*tanh(0.5*sigma*(v-mu))
//   -> arg = fma(v, 0.5*sigma, -0.5*sigma*mu); contribution w*sig = 0.5w + (0.5w)*tanh
// constants 0.5*sum(w) folded into g_nadd/g_dadd by prep2.
__global__ void prep_kernel(const float* __restrict__ w, const float* __restrict__ sigma,
                            const float* __restrict__ mu, const float* __restrict__ erev,
                            const float* __restrict__ mask,
                            const float* __restrict__ sw, const float* __restrict__ ssig,
                            const float* __restrict__ smu, const float* __restrict__ serev,
                            const float* __restrict__ smask,
                            const float* __restrict__ gleak, const float* __restrict__ vleak,
                            const float* __restrict__ cm)
{
    int idx = blockIdx.x * blockDim.x + threadIdx.x;
    if (idx < SS * SS) {
        int j = idx / SS, k = idx % SS;
        float sg = sigma[idx], m = mu[idx];
        g_RA1[k * SS + j] = 0.5f * sg;
        g_RA2[k * SS + j] = -0.5f * sg * m;
        g_RWN[idx] = 0.5f * w[idx] * mask[idx] * erev[idx];   // [j][k], halved, signed
    }
    int i2 = idx - SS * SS;
    if (i2 >= 0 && i2 < II * SS) {
        float sg = ssig[i2], m = smu[i2];
        g_SA1[i2] = 0.5f * sg;
        g_SA2[i2] = -0.5f * sg * m;
        g_SWN[i2] = 0.5f * sw[i2] * smask[i2] * serev[i2];
    }
    int i3 = idx - SS * SS - II * SS;
    if (i3 >= 0 && i3 < SS) {
        float c = cm[i3] * 6.0f;               // cm / (ELAPSED/ODE_UNFOLDS)
        g_cmt[i3]  = c;
        g_nadd[i3] = gleak[i3] * vleak[i3];
        g_dadd[i3] = c + gleak[i3] + 1e-8f;
    }
}

// fold 0.5*sum(w), 0.5*sum(|w|) (recurrent + sensory) into the additive constants
__global__ void prep2_kernel()
{
    int k = threadIdx.x;
    float ns = 0.f, ds = 0.f;
    for (int j = 0; j < SS; j++) {
        float x = g_RWN[j * SS + k];
        ns += x; ds += fabsf(x);
    }
    for (int i = 0; i < II; i++) {
        float x = g_SWN[i * SS + k];
        ns += x; ds += fabsf(x);
    }
    g_nadd[k] += ns;
    g_dadd[k] += ds;
}

// ---------------- generic tiled SIMT GEMM (BM=128, BN=64, BK=16, 256 thr) ----------------
template <int ACT>
__global__ void __launch_bounds__(256) gemm_kernel(const float* __restrict__ A, int lda,
                                                   const float* __restrict__ B, int ldb,
                                                   const float* __restrict__ bias,
                                                   float* __restrict__ C, int ldc, int K)
{
    __shared__ float As[16][128];
    __shared__ float Bs[16][64];
    int tid = threadIdx.x;
    int bm = blockIdx.y * 128;
    int bn = blockIdx.x * 64;
    int tx = tid & 15, ty = tid >> 4;
    int a_m = tid >> 2;
    int a_k = (tid & 3) * 4;
    int b_k = tid >> 4;
    int b_n = (tid & 15) * 4;

    float acc[8][4];
#pragma unroll
    for (int i = 0; i < 8; i++)
#pragma unroll
        for (int j = 0; j < 4; j++) acc[i][j] = 0.f;

    for (int k0 = 0; k0 < K; k0 += 16) {
#pragma unroll
        for (int i = 0; i < 2; i++) {
            float4 va = *(const float4*)(A + (size_t)(bm + a_m + i * 64) * lda + k0 + a_k);
            As[a_k + 0][a_m + i * 64] = va.x;
            As[a_k + 1][a_m + i * 64] = va.y;
            As[a_k + 2][a_m + i * 64] = va.z;
            As[a_k + 3][a_m + i * 64] = va.w;
        }
        *(float4*)(&Bs[b_k][b_n]) = *(const float4*)(B + (size_t)(k0 + b_k) * ldb + bn + b_n);
        __syncthreads();
#pragma unroll
        for (int kk = 0; kk < 16; kk++) {
            float a[8], bv[4];
#pragma unroll
            for (int i = 0; i < 8; i++) a[i] = As[kk][ty * 8 + i];
#pragma unroll
            for (int j = 0; j < 4; j++) bv[j] = Bs[kk][tx * 4 + j];
#pragma unroll
            for (int i = 0; i < 8; i++)
#pragma unroll
                for (int j = 0; j < 4; j++) acc[i][j] = fmaf(a[i], bv[j], acc[i][j]);
        }
        __syncthreads();
    }
    float4 bb = *(const float4*)(bias + bn + tx * 4);
    float bv4[4] = {bb.x, bb.y, bb.z, bb.w};
#pragma unroll
    for (int i = 0; i < 8; i++) {
        int m = bm + ty * 8 + i;
        float4 o;
        float v0 = acc[i][0] + bv4[0], v1 = acc[i][1] + bv4[1];
        float v2 = acc[i][2] + bv4[2], v3 = acc[i][3] + bv4[3];
        if (ACT == 1) { v0 = tanhf(v0); v1 = tanhf(v1); v2 = tanhf(v2); v3 = tanhf(v3); }
        o.x = v0; o.y = v1; o.z = v2; o.w = v3;
        *(float4*)(C + (size_t)m * ldc + bn + tx * 4) = o;
    }
}

// ---------------- softmax over T (axis=1) + fold sigmoid into CG ----------------
// gate = tanh(...) in (-1,1): exp is safe without max subtraction; softmax identical.
__global__ void __launch_bounds__(256) softmax_cg_kernel()
{
    int b = blockIdx.y;
    int s0 = blockIdx.x * 32;
    int s = threadIdx.x & 31;
    int g = threadIdx.x >> 5;          // 0..7
    __shared__ float red[8][32];
    __shared__ float rsh[32];

    const float* gp = g_proj + (size_t)b * TT_ * NPROJ + II + s0 + s;
    float sum = 0.f;
#pragma unroll 4
    for (int t = g * 128; t < g * 128 + 128; t++)
        sum += __expf(gp[(size_t)t * NPROJ]);
    red[g][s] = sum;
    __syncthreads();
    if (g == 0) {
        float tot = 0.f;
#pragma unroll
        for (int i = 0; i < 8; i++) tot += red[i][s];
        rsh[s] = __fdividef(1.f, tot);
    }
    __syncthreads();
    float rs = rsh[s];
    float* cg = g_CG + (size_t)b * TT_ * SS + s0 + s;
#pragma unroll 4
    for (int t = g * 128; t < g * 128 + 128; t++) {
        float p = __expf(gp[(size_t)t * NPROJ]) * rs;
        float sg = __fdividef(1.f, 1.f + __expf(-p));
        cg[(size_t)t * SS] *= sg;
    }
}

// ---------------- sensory precompute: per (b,t,k) w_num_s/w_den_s ----------------
__global__ void __launch_bounds__(128) sensory_kernel()
{
    int blk = blockIdx.x;
    int b = blk >> 6;                  // T/STT = 64
    int t0 = (blk & 63) * STT;
    __shared__ float sh[STT][II];
    int tid = threadIdx.x;
    size_t rowbase = (size_t)b * TT_ + t0;
    for (int idx = tid; idx < STT * II; idx += 128) {
        int tt = idx >> 8, i = idx & 255;
        sh[tt][i] = g_proj[(rowbase + tt) * NPROJ + i];
    }
    __syncthreads();
    int k = tid;
    float num[STT], den[STT];
#pragma unroll
    for (int tt = 0; tt < STT; tt++) { num[tt] = 0.f; den[tt] = 0.f; }
    for (int i = 0; i < II; i++) {
        float a1 = g_SA1[i * SS + k];
        float a2 = g_SA2[i * SS + k];
        float wv = g_SWN[i * SS + k];
        float aw = fabsf(wv);
#pragma unroll
        for (int tt = 0; tt < STT; tt++) {
            float th = tanh_fast(fmaf(sh[tt][i], a1, a2));
            num[tt] = fmaf(wv, th, num[tt]);
            den[tt] = fmaf(aw, th, den[tt]);
        }
    }
    float na = g_nadd[k], da = g_dadd[k];
#pragma unroll
    for (int tt = 0; tt < STT; tt++) {
        size_t row = rowbase + tt;
        g_wns[row * SS + k] = num[tt] + na;
        g_wds[row * SS + k] = den[tt] + da;
    }
}

// ---------------- sequential ODE scan: 1 CTA per batch, 512 threads ----------------
// thread (k = tid&127, h = tid>>7) handles j in [h*32, h*32+32).
// a1/a2 coefficient slices live in registers; halved signed weights in smem [j][k]
// (conflict-free LDS.32); v[j] reads are warp-uniform broadcasts.
#define SCAN_SMEM ((SS * SS + SS + 2 * 4 * SS) * 4)

__global__ void __launch_bounds__(512, 1) scan_kernel(const float* __restrict__ v0,
                                                      float* __restrict__ fused_out,
                                                      float* __restrict__ vfinal)
{
    extern __shared__ float smem[];
    float* swt  = smem;                  // [j][k] 128x128
    float* sv   = swt + SS * SS;         // 128
    float* snum = sv + SS;               // 4x128
    float* sden = snum + 4 * SS;         // 4x128

    int b = blockIdx.x;
    int tid = threadIdx.x;
    int k = tid & 127;
    int h = tid >> 7;
    int j0 = h * 32;

    // weights into smem (coalesced copy, [j][k] layout preserved)
    for (int idx = tid; idx < SS * SS; idx += 512) swt[idx] = g_RWN[idx];

    // per-thread coefficient registers
    float wa1[32], wa2[32];
#pragma unroll
    for (int q = 0; q < 32; q++) {
        wa1[q] = g_RA1[k * SS + j0 + q];
        wa2[q] = g_RA2[k * SS + j0 + q];
    }

    float cmt = 0.f, vk = 0.f;
    if (h == 0) {
        cmt = g_cmt[k];
        vk = v0[b * SS + k];
        sv[k] = vk;
    }
    __syncthreads();

    size_t row = (size_t)b * TT_;

#pragma unroll 1
    for (int t = 0; t < TT_; t++, row++) {
        float wns = 0.f, wds = 0.f, cg = 0.f;
        if (h == 0) {
            wns = g_wns[row * SS + k];
            wds = g_wds[row * SS + k];
            cg  = g_CG [row * SS + k];
        }
#pragma unroll 1
        for (int u = 0; u < 6; u++) {
            float num = 0.f, den = 0.f;
#pragma unroll
            for (int q = 0; q < 32; q++) {
                float vj = sv[j0 + q];                       // warp-uniform broadcast
                float wv = swt[(j0 + q) * SS + k];           // conflict-free LDS.32
                float th = tanh_fast(fmaf(vj, wa1[q], wa2[q]));
                num = fmaf(wv, th, num);
                den = fmaf(fabsf(wv), th, den);
            }
            snum[h * SS + k] = num;
            sden[h * SS + k] = den;
            __syncthreads();
            if (h == 0) {
                float nt = wns + snum[k] + snum[SS + k] + snum[2 * SS + k] + snum[3 * SS + k];
                float dt = wds + sden[k] + sden[SS + k] + sden[2 * SS + k] + sden[3 * SS + k];
                nt = fmaf(cmt, vk, nt);
                vk = nt * __fdividef(1.f, dt);
                sv[k] = vk;
            }
            __syncthreads();
        }
        if (h == 0) fused_out[row * SS + k] = vk * cg;
    }
    if (h == 0) vfinal[b * SS + k] = vk;
}

// ---------------- launch ----------------
extern "C" void kernel_launch(void* const* d_in, const int* in_sizes, int n_in,
                              void* d_out, int out_size)
{
    const float* inputs    = (const float*)d_in[0];
    const float* ode_state = (const float*)d_in[1];
    const float* W_in      = (const float*)d_in[2];
    const float* b_in      = (const float*)d_in[3];
    const float* W_c       = (const float*)d_in[4];
    const float* b_c       = (const float*)d_in[5];
    const float* W_out     = (const float*)d_in[6];
    const float* b_out     = (const float*)d_in[7];
    const float* gleak     = (const float*)d_in[8];
    const float* vleak     = (const float*)d_in[9];
    const float* cm        = (const float*)d_in[10];
    const float* w         = (const float*)d_in[11];
    const float* sigma     = (const float*)d_in[12];
    const float* mu        = (const float*)d_in[13];
    const float* sw        = (const float*)d_in[14];
    const float* ssig      = (const float*)d_in[15];
    const float* smu       = (const float*)d_in[16];
    const float* erev      = (const float*)d_in[17];
    const float* serev     = (const float*)d_in[18];
    const float* mask      = (const float*)d_in[19];
    const float* smask     = (const float*)d_in[20];

    float* out      = (float*)d_out;                          // (B,T,M)
    float* vfinal   = out + (size_t)BB * TT_ * MM;            // (B,S)
    float* fusedout = vfinal + (size_t)BB * SS;               // (B,T,S)

    float *p_proj, *p_cg;
    cudaGetSymbolAddress((void**)&p_proj, g_proj);
    cudaGetSymbolAddress((void**)&p_cg, g_CG);

    cudaFuncSetAttribute(scan_kernel, cudaFuncAttributeMaxDynamicSharedMemorySize, SCAN_SMEM);

    int prep_n = SS * SS + II * SS + SS;
    prep_kernel<<<(prep_n + 255) / 256, 256>>>(w, sigma, mu, erev, mask,
                                               sw, ssig, smu, serev, smask,
                                               gleak, vleak, cm);
    prep2_kernel<<<1, 128>>>();

    // proj = tanh(inputs @ W_in + b_in)
    gemm_kernel<1><<<dim3(NPROJ / 64, (BB * TT_) / 128), 256>>>(
        inputs, FF, W_in, NPROJ, b_in, p_proj, NPROJ, FF);

    // CG = hidden @ W_c + b_c   (hidden = proj[:, :256], lda=384)
    gemm_kernel<0><<<dim3(SS / 64, (BB * TT_) / 128), 256>>>(
        p_proj, NPROJ, W_c, SS, b_c, p_cg, SS, II);

    // CG *= sigmoid(softmax_T(gate))
    softmax_cg_kernel<<<dim3(4, BB), 256>>>();

    // sensory num/den precompute
    sensory_kernel<<<BB * (TT_ / STT), 128>>>();

    // sequential scan: writes fused (B,T,S) and final state directly into d_out
    scan_kernel<<<BB, 512, SCAN_SMEM>>>(ode_state, fusedout, vfinal);

    // outputs = fused @ W_out + b_out
    gemm_kernel<0><<<dim3(MM / 64, (BB * TT_) / 128), 256>>>(
        fusedout, SS, W_out, MM, b_out, out, MM, SS);
}

// round 3
// speedup vs baseline: 1.7862x; 1.0006x over previous
#include <cuda_runtime.h>
#include <math.h>
#include <stdint.h>

#define BB 64
#define TT_ 1024
#define FF 512
#define II 256
#define SS 128
#define MM 64
#define NPROJ 384
#define STT 16

// ---------------- scratch (static device globals; no allocation) ----------------
__device__ float g_proj[(size_t)BB * TT_ * NPROJ];   // tanh(inputs@W_in+b)  (B*T, 384)
__device__ float g_CG [(size_t)BB * TT_ * SS];       // C * sigmoid(softmax(gate))
__device__ float g_wns[(size_t)BB * TT_ * SS];       // sensory num + all per-k num consts
__device__ float g_wds[(size_t)BB * TT_ * SS];       // sensory den + all per-k den consts
__device__ float g_RA1[SS * SS], g_RA2[SS * SS];     // recurrent 0.5*sigma / -0.5*sigma*mu, [k][j]
__device__ float g_RWN[SS * SS];                     // 0.5*w*mask*erev, [j][k]
__device__ float g_SA1[II * SS], g_SA2[II * SS], g_SWN[II * SS];   // sensory, [i][k]
__device__ float g_cmt[SS], g_nadd[SS], g_dadd[SS];

__device__ __forceinline__ float tanh_fast(float x) {
    float r;
    asm("tanh.approx.f32 %0, %1;" : "=f"(r) : "f"(x));
    return r;
}

// ---------------- param preprocessing ----------------
// sigmoid((v-mu)*sigma) = 0.5 + 0.5*tanh(0.5*sigma*(v-mu))
//   -> arg = fma(v, 0.5*sigma, -0.5*sigma*mu); contribution w*sig = 0.5w + (0.5w)*tanh
// constants 0.5*sum(w) folded into g_nadd/g_dadd by prep2.
__global__ void prep_kernel(const float* __restrict__ w, const float* __restrict__ sigma,
                            const float* __restrict__ mu, const float* __restrict__ erev,
                            const float* __restrict__ mask,
                            const float* __restrict__ sw, const float* __restrict__ ssig,
                            const float* __restrict__ smu, const float* __restrict__ serev,
                            const float* __restrict__ smask,
                            const float* __restrict__ gleak, const float* __restrict__ vleak,
                            const float* __restrict__ cm)
{
    int idx = blockIdx.x * blockDim.x + threadIdx.x;
    if (idx < SS * SS) {
        int j = idx / SS, k = idx % SS;
        float sg = sigma[idx], m = mu[idx];
        g_RA1[k * SS + j] = 0.5f * sg;
        g_RA2[k * SS + j] = -0.5f * sg * m;
        g_RWN[idx] = 0.5f * w[idx] * mask[idx] * erev[idx];   // [j][k], halved, signed
    }
    int i2 = idx - SS * SS;
    if (i2 >= 0 && i2 < II * SS) {
        float sg = ssig[i2], m = smu[i2];
        g_SA1[i2] = 0.5f * sg;
        g_SA2[i2] = -0.5f * sg * m;
        g_SWN[i2] = 0.5f * sw[i2] * smask[i2] * serev[i2];
    }
    int i3 = idx - SS * SS - II * SS;
    if (i3 >= 0 && i3 < SS) {
        float c = cm[i3] * 6.0f;               // cm / (ELAPSED/ODE_UNFOLDS)
        g_cmt[i3]  = c;
        g_nadd[i3] = gleak[i3] * vleak[i3];
        g_dadd[i3] = c + gleak[i3] + 1e-8f;
    }
}

// fold 0.5*sum(w), 0.5*sum(|w|) (recurrent + sensory) into the additive constants
__global__ void prep2_kernel()
{
    int k = threadIdx.x;
    float ns = 0.f, ds = 0.f;
    for (int j = 0; j < SS; j++) {
        float x = g_RWN[j * SS + k];
        ns += x; ds += fabsf(x);
    }
    for (int i = 0; i < II; i++) {
        float x = g_SWN[i * SS + k];
        ns += x; ds += fabsf(x);
    }
    g_nadd[k] += ns;
    g_dadd[k] += ds;
}

// ---------------- generic tiled SIMT GEMM (BM=128, BN=64, BK=16, 256 thr) ----------------
template <int ACT>
__global__ void __launch_bounds__(256) gemm_kernel(const float* __restrict__ A, int lda,
                                                   const float* __restrict__ B, int ldb,
                                                   const float* __restrict__ bias,
                                                   float* __restrict__ C, int ldc, int K)
{
    __shared__ float As[16][128];
    __shared__ float Bs[16][64];
    int tid = threadIdx.x;
    int bm = blockIdx.y * 128;
    int bn = blockIdx.x * 64;
    int tx = tid & 15, ty = tid >> 4;
    int a_m = tid >> 2;
    int a_k = (tid & 3) * 4;
    int b_k = tid >> 4;
    int b_n = (tid & 15) * 4;

    float acc[8][4];
#pragma unroll
    for (int i = 0; i < 8; i++)
#pragma unroll
        for (int j = 0; j < 4; j++) acc[i][j] = 0.f;

    for (int k0 = 0; k0 < K; k0 += 16) {
#pragma unroll
        for (int i = 0; i < 2; i++) {
            float4 va = *(const float4*)(A + (size_t)(bm + a_m + i * 64) * lda + k0 + a_k);
            As[a_k + 0][a_m + i * 64] = va.x;
            As[a_k + 1][a_m + i * 64] = va.y;
            As[a_k + 2][a_m + i * 64] = va.z;
            As[a_k + 3][a_m + i * 64] = va.w;
        }
        *(float4*)(&Bs[b_k][b_n]) = *(const float4*)(B + (size_t)(k0 + b_k) * ldb + bn + b_n);
        __syncthreads();
#pragma unroll
        for (int kk = 0; kk < 16; kk++) {
            float a[8], bv[4];
#pragma unroll
            for (int i = 0; i < 8; i++) a[i] = As[kk][ty * 8 + i];
#pragma unroll
            for (int j = 0; j < 4; j++) bv[j] = Bs[kk][tx * 4 + j];
#pragma unroll
            for (int i = 0; i < 8; i++)
#pragma unroll
                for (int j = 0; j < 4; j++) acc[i][j] = fmaf(a[i], bv[j], acc[i][j]);
        }
        __syncthreads();
    }
    float4 bb = *(const float4*)(bias + bn + tx * 4);
    float bv4[4] = {bb.x, bb.y, bb.z, bb.w};
#pragma unroll
    for (int i = 0; i < 8; i++) {
        int m = bm + ty * 8 + i;
        float4 o;
        float v0 = acc[i][0] + bv4[0], v1 = acc[i][1] + bv4[1];
        float v2 = acc[i][2] + bv4[2], v3 = acc[i][3] + bv4[3];
        if (ACT == 1) { v0 = tanhf(v0); v1 = tanhf(v1); v2 = tanhf(v2); v3 = tanhf(v3); }
        o.x = v0; o.y = v1; o.z = v2; o.w = v3;
        *(float4*)(C + (size_t)m * ldc + bn + tx * 4) = o;
    }
}

// ---------------- softmax over T (axis=1) + fold sigmoid into CG ----------------
// gate = tanh(...) in (-1,1): exp is safe without max subtraction; softmax identical.
__global__ void __launch_bounds__(256) softmax_cg_kernel()
{
    int b = blockIdx.y;
    int s0 = blockIdx.x * 32;
    int s = threadIdx.x & 31;
    int g = threadIdx.x >> 5;          // 0..7
    __shared__ float red[8][32];
    __shared__ float rsh[32];

    const float* gp = g_proj + (size_t)b * TT_ * NPROJ + II + s0 + s;
    float sum = 0.f;
#pragma unroll 4
    for (int t = g * 128; t < g * 128 + 128; t++)
        sum += __expf(gp[(size_t)t * NPROJ]);
    red[g][s] = sum;
    __syncthreads();
    if (g == 0) {
        float tot = 0.f;
#pragma unroll
        for (int i = 0; i < 8; i++) tot += red[i][s];
        rsh[s] = __fdividef(1.f, tot);
    }
    __syncthreads();
    float rs = rsh[s];
    float* cg = g_CG + (size_t)b * TT_ * SS + s0 + s;
#pragma unroll 4
    for (int t = g * 128; t < g * 128 + 128; t++) {
        float p = __expf(gp[(size_t)t * NPROJ]) * rs;
        float sg = __fdividef(1.f, 1.f + __expf(-p));
        cg[(size_t)t * SS] *= sg;
    }
}

// ---------------- sensory precompute: per (b,t,k) w_num_s/w_den_s ----------------
__global__ void __launch_bounds__(128) sensory_kernel()
{
    int blk = blockIdx.x;
    int b = blk >> 6;                  // T/STT = 64
    int t0 = (blk & 63) * STT;
    __shared__ float sh[STT][II];
    int tid = threadIdx.x;
    size_t rowbase = (size_t)b * TT_ + t0;
    for (int idx = tid; idx < STT * II; idx += 128) {
        int tt = idx >> 8, i = idx & 255;
        sh[tt][i] = g_proj[(rowbase + tt) * NPROJ + i];
    }
    __syncthreads();
    int k = tid;
    float num[STT], den[STT];
#pragma unroll
    for (int tt = 0; tt < STT; tt++) { num[tt] = 0.f; den[tt] = 0.f; }
    for (int i = 0; i < II; i++) {
        float a1 = g_SA1[i * SS + k];
        float a2 = g_SA2[i * SS + k];
        float wv = g_SWN[i * SS + k];
        float aw = fabsf(wv);
#pragma unroll
        for (int tt = 0; tt < STT; tt++) {
            float th = tanh_fast(fmaf(sh[tt][i], a1, a2));
            num[tt] = fmaf(wv, th, num[tt]);
            den[tt] = fmaf(aw, th, den[tt]);
        }
    }
    float na = g_nadd[k], da = g_dadd[k];
#pragma unroll
    for (int tt = 0; tt < STT; tt++) {
        size_t row = rowbase + tt;
        g_wns[row * SS + k] = num[tt] + na;
        g_wds[row * SS + k] = den[tt] + da;
    }
}

// ---------------- sequential ODE scan: 1 CTA per batch, 512 threads ----------------
// thread (k = tid&127, h = tid>>7) handles j in [h*32, h*32+32).
// a1/a2 coefficient slices live in registers; halved signed weights in smem [j][k]
// (conflict-free LDS.32); v[j] reads are warp-uniform broadcasts.
#define SCAN_SMEM ((SS * SS + SS + 2 * 4 * SS) * 4)

__global__ void __launch_bounds__(512, 1) scan_kernel(const float* __restrict__ v0,
                                                      float* __restrict__ fused_out,
                                                      float* __restrict__ vfinal)
{
    extern __shared__ float smem[];
    float* swt  = smem;                  // [j][k] 128x128
    float* sv   = swt + SS * SS;         // 128
    float* snum = sv + SS;               // 4x128
    float* sden = snum + 4 * SS;         // 4x128

    int b = blockIdx.x;
    int tid = threadIdx.x;
    int k = tid & 127;
    int h = tid >> 7;
    int j0 = h * 32;

    // weights into smem (coalesced copy, [j][k] layout preserved)
    for (int idx = tid; idx < SS * SS; idx += 512) swt[idx] = g_RWN[idx];

    // per-thread coefficient registers
    float wa1[32], wa2[32];
#pragma unroll
    for (int q = 0; q < 32; q++) {
        wa1[q] = g_RA1[k * SS + j0 + q];
        wa2[q] = g_RA2[k * SS + j0 + q];
    }

    float cmt = 0.f, vk = 0.f;
    if (h == 0) {
        cmt = g_cmt[k];
        vk = v0[b * SS + k];
        sv[k] = vk;
    }
    __syncthreads();

    size_t row = (size_t)b * TT_;

#pragma unroll 1
    for (int t = 0; t < TT_; t++, row++) {
        float wns = 0.f, wds = 0.f, cg = 0.f;
        if (h == 0) {
            wns = g_wns[row * SS + k];
            wds = g_wds[row * SS + k];
            cg  = g_CG [row * SS + k];
        }
#pragma unroll 1
        for (int u = 0; u < 6; u++) {
            float num = 0.f, den = 0.f;
#pragma unroll
            for (int q = 0; q < 32; q++) {
                float vj = sv[j0 + q];                       // warp-uniform broadcast
                float wv = swt[(j0 + q) * SS + k];           // conflict-free LDS.32
                float th = tanh_fast(fmaf(vj, wa1[q], wa2[q]));
                num = fmaf(wv, th, num);
                den = fmaf(fabsf(wv), th, den);
            }
            snum[h * SS + k] = num;
            sden[h * SS + k] = den;
            __syncthreads();
            if (h == 0) {
                float nt = wns + snum[k] + snum[SS + k] + snum[2 * SS + k] + snum[3 * SS + k];
                float dt = wds + sden[k] + sden[SS + k] + sden[2 * SS + k] + sden[3 * SS + k];
                nt = fmaf(cmt, vk, nt);
                vk = nt * __fdividef(1.f, dt);
                sv[k] = vk;
            }
            __syncthreads();
        }
        if (h == 0) fused_out[row * SS + k] = vk * cg;
    }
    if (h == 0) vfinal[b * SS + k] = vk;
}

// ---------------- launch ----------------
extern "C" void kernel_launch(void* const* d_in, const int* in_sizes, int n_in,
                              void* d_out, int out_size)
{
    const float* inputs    = (const float*)d_in[0];
    const float* ode_state = (const float*)d_in[1];
    const float* W_in      = (const float*)d_in[2];
    const float* b_in      = (const float*)d_in[3];
    const float* W_c       = (const float*)d_in[4];
    const float* b_c       = (const float*)d_in[5];
    const float* W_out     = (const float*)d_in[6];
    const float* b_out     = (const float*)d_in[7];
    const float* gleak     = (const float*)d_in[8];
    const float* vleak     = (const float*)d_in[9];
    const float* cm        = (const float*)d_in[10];
    const float* w         = (const float*)d_in[11];
    const float* sigma     = (const float*)d_in[12];
    const float* mu        = (const float*)d_in[13];
    const float* sw        = (const float*)d_in[14];
    const float* ssig      = (const float*)d_in[15];
    const float* smu       = (const float*)d_in[16];
    const float* erev      = (const float*)d_in[17];
    const float* serev     = (const float*)d_in[18];
    const float* mask      = (const float*)d_in[19];
    const float* smask     = (const float*)d_in[20];

    float* out      = (float*)d_out;                          // (B,T,M)
    float* vfinal   = out + (size_t)BB * TT_ * MM;            // (B,S)
    float* fusedout = vfinal + (size_t)BB * SS;               // (B,T,S)

    float *p_proj, *p_cg;
    cudaGetSymbolAddress((void**)&p_proj, g_proj);
    cudaGetSymbolAddress((void**)&p_cg, g_CG);

    cudaFuncSetAttribute(scan_kernel, cudaFuncAttributeMaxDynamicSharedMemorySize, SCAN_SMEM);

    int prep_n = SS * SS + II * SS + SS;
    prep_kernel<<<(prep_n + 255) / 256, 256>>>(w, sigma, mu, erev, mask,
                                               sw, ssig, smu, serev, smask,
                                               gleak, vleak, cm);
    prep2_kernel<<<1, 128>>>();

    // proj = tanh(inputs @ W_in + b_in)
    gemm_kernel<1><<<dim3(NPROJ / 64, (BB * TT_) / 128), 256>>>(
        inputs, FF, W_in, NPROJ, b_in, p_proj, NPROJ, FF);

    // CG = hidden @ W_c + b_c   (hidden = proj[:, :256], lda=384)
    gemm_kernel<0><<<dim3(SS / 64, (BB * TT_) / 128), 256>>>(
        p_proj, NPROJ, W_c, SS, b_c, p_cg, SS, II);

    // CG *= sigmoid(softmax_T(gate))
    softmax_cg_kernel<<<dim3(4, BB), 256>>>();

    // sensory num/den precompute
    sensory_kernel<<<BB * (TT_ / STT), 128>>>();

    // sequential scan: writes fused (B,T,S) and final state directly into d_out
    scan_kernel<<<BB, 512, SCAN_SMEM>>>(ode_state, fusedout, vfinal);

    // outputs = fused @ W_out + b_out
    gemm_kernel<0><<<dim3(MM / 64, (BB * TT_) / 128), 256>>>(
        fusedout, SS, W_out, MM, b_out, out, MM, SS);
}